// round 15
// baseline (speedup 1.0000x reference)
#include <cuda_runtime.h>

// Problem constants
#define I_IN   21
#define H      50
#define G      200          // 4*H, gate order: i, f, g, o
#define GP     100          // gate pairs
#define BATCH  4096
#define T      336
#define OUT    24
#define VK     72           // padded k length: [x_t(21) | h(50) | 0]
#define VST    33           // vsT row stride (pad 32->33: conflict-free h writes)
#define KW2    72           // Wp row length in float2 (even -> 16B-aligned float4 loads)
#define BT     32           // batch rows per CTA (= lanes per warp)
#define NTHREADS 320        // 10 warps; warp w owns gate-pairs [w*10, w*10+10)
#define NCTAS  (BATCH / BT) // 128

// shared layout (floats):
//   Wp    [GP*KW2*2]  = 14400  paired weights: float2 = (W[2gp][k], W[2gp+1][k])
//   vsT   [VK*VST]    = 2376   transposed state: vsT[k][b]
//   g2f   [GP*BT*2]   = 6400   transposed gates: float2 (even,odd) per (gp,b)
//   bias2 [G]         = 200    paired bias (b_ih+b_hh), layout [gp*2+c]
//   Wfc   [OUT*H]     = 1200
//   bfc   [OUT]       = 24
#define OFF_WP    0
#define OFF_VST   (OFF_WP  + GP*KW2*2)
#define OFF_G2F   (OFF_VST + VK*VST + 1)   // +1 -> keep 8B alignment? 2376 even, +1 odd. Use no pad:
#undef  OFF_G2F
#define OFF_G2F   (OFF_VST + VK*VST)       // 14400+2376 = 16776 (even -> 8B aligned)
#define OFF_BIAS  (OFF_G2F + GP*BT*2)      // 23176 (even)
#define OFF_WFC   (OFF_BIAS + G)
#define OFF_BFC   (OFF_WFC + OUT*H)
#define SMEM_FLOATS (OFF_BFC + OUT)

__device__ __forceinline__ float tanh_fast(float x) {
    float y;
    asm("tanh.approx.f32 %0, %1;" : "=f"(y) : "f"(x));
    return y;
}
__device__ __forceinline__ float sig_fast(float x) {
    return fmaf(0.5f, tanh_fast(0.5f * x), 0.5f);
}
__device__ __forceinline__ unsigned long long dup_f32(float v) {
    unsigned long long r;
    asm("mov.b64 %0, {%1, %1};" : "=l"(r) : "f"(v));
    return r;
}
__device__ __forceinline__ void fma2(unsigned long long& acc,
                                     unsigned long long a, unsigned long long b) {
    asm("fma.rn.f32x2 %0, %1, %2, %0;" : "+l"(acc) : "l"(a), "l"(b));
}

__global__ __launch_bounds__(NTHREADS, 1)
void lstm_persistent_kernel(const float* __restrict__ x,
                            const float* __restrict__ W_ih,
                            const float* __restrict__ W_hh,
                            const float* __restrict__ b_ih,
                            const float* __restrict__ b_hh,
                            const float* __restrict__ W_fc,
                            const float* __restrict__ b_fc,
                            float* __restrict__ out)
{
    extern __shared__ float smem[];
    float* Wp    = smem + OFF_WP;     // [GP][KW2] float2
    float* vsT   = smem + OFF_VST;    // [VK][VST]
    float* g2f   = smem + OFF_G2F;    // [GP][BT] float2
    float* bias2 = smem + OFF_BIAS;   // [GP] float2
    float* Wfcs  = smem + OFF_WFC;
    float* bfcs  = smem + OFF_BFC;

    const int tid  = threadIdx.x;
    const int lane = tid & 31;
    const int wid  = tid >> 5;
    const int b0   = blockIdx.x * BT;

    // ---- one-time loads into shared ----
    // Paired weights: Wp[gp][k] = (Wc[2gp][k], Wc[2gp+1][k])
    for (int idx = tid; idx < GP * KW2; idx += NTHREADS) {
        int gp = idx / KW2, k = idx % KW2;
        float v0 = 0.0f, v1 = 0.0f;
        int g0 = 2 * gp, g1 = 2 * gp + 1;
        if (k < I_IN) {
            v0 = W_ih[g0 * I_IN + k];
            v1 = W_ih[g1 * I_IN + k];
        } else if (k < I_IN + H) {
            v0 = W_hh[g0 * H + (k - I_IN)];
            v1 = W_hh[g1 * H + (k - I_IN)];
        }
        Wp[idx * 2 + 0] = v0;
        Wp[idx * 2 + 1] = v1;
    }
    for (int idx = tid; idx < G; idx += NTHREADS) bias2[idx] = b_ih[idx] + b_hh[idx];
    for (int idx = tid; idx < OUT * H; idx += NTHREADS) Wfcs[idx] = W_fc[idx];
    if (tid < OUT) bfcs[tid] = b_fc[tid];

    // init state (h rows + pads) to zero
    for (int idx = tid; idx < VK * VST; idx += NTHREADS) vsT[idx] = 0.0f;
    __syncthreads();
    // load x_0 into transposed state
    for (int idx = tid; idx < BT * I_IN; idx += NTHREADS) {
        int b = idx / I_IN, i = idx % I_IN;
        vsT[i * VST + b] = x[(size_t)(b0 + b) * T * I_IN + i];
    }
    __syncthreads();

    const int gp0 = wid * 10;   // this warp's 10 gate-pairs

    float creg[5];              // cell state for phase-2 units (tid*5 + j)
#pragma unroll
    for (int j = 0; j < 5; j++) creg[j] = 0.0f;

    for (int t = 0; t < T; ++t) {
        // ---- prefetch x_{t+1} into registers (covered by phase-1 compute) ----
        float xr[3];
        if (t + 1 < T) {
#pragma unroll
            for (int u = 0; u < 3; u++) {
                int idx = tid + u * NTHREADS;
                if (idx < BT * I_IN) {
                    int b = idx / I_IN, i = idx % I_IN;
                    xr[u] = x[(size_t)(b0 + b) * T * I_IN + (size_t)(t + 1) * I_IN + i];
                }
            }
        }

        // ---- phase 1: gates (f32x2, lane = batch, warp-uniform weight loads) ----
        unsigned long long acc[10];
#pragma unroll
        for (int j = 0; j < 10; j++)
            acc[j] = *(const unsigned long long*)&bias2[(gp0 + j) * 2];

#pragma unroll 3
        for (int k = 0; k < VK; k += 4) {
            float v0 = vsT[(k + 0) * VST + lane];
            float v1 = vsT[(k + 1) * VST + lane];
            float v2 = vsT[(k + 2) * VST + lane];
            float v3 = vsT[(k + 3) * VST + lane];
            unsigned long long vp0 = dup_f32(v0);
            unsigned long long vp1 = dup_f32(v1);
            unsigned long long vp2 = dup_f32(v2);
            unsigned long long vp3 = dup_f32(v3);
#pragma unroll
            for (int j = 0; j < 10; j++) {
                const float* wr = &Wp[((gp0 + j) * KW2 + k) * 2];
                ulonglong2 wa = *(const ulonglong2*)(wr);      // k, k+1
                ulonglong2 wb = *(const ulonglong2*)(wr + 4);  // k+2, k+3
                fma2(acc[j], wa.x, vp0);
                fma2(acc[j], wa.y, vp1);
                fma2(acc[j], wb.x, vp2);
                fma2(acc[j], wb.y, vp3);
            }
        }
#pragma unroll
        for (int j = 0; j < 10; j++)
            *(unsigned long long*)&g2f[((gp0 + j) * BT + lane) * 2] = acc[j];
        __syncthreads();

        // ---- phase 2: state update (+ commit prefetched x_{t+1}) ----
        if (t + 1 < T) {
#pragma unroll
            for (int u = 0; u < 3; u++) {
                int idx = tid + u * NTHREADS;
                if (idx < BT * I_IN)
                    vsT[(idx % I_IN) * VST + (idx / I_IN)] = xr[u];
            }
        }
#pragma unroll
        for (int j = 0; j < 5; j++) {
            int p   = tid * 5 + j;        // 0..1599
            int b   = p / H;
            int hu  = p % H;
            int gpi = hu >> 1;
            int par = hu & 1;
            float ig = sig_fast (g2f[((     gpi) * BT + b) * 2 + par]);
            float fg = sig_fast (g2f[((25 + gpi) * BT + b) * 2 + par]);
            float gg = tanh_fast(g2f[((50 + gpi) * BT + b) * 2 + par]);
            float og = sig_fast (g2f[((75 + gpi) * BT + b) * 2 + par]);
            float c  = fmaf(fg, creg[j], ig * gg);
            creg[j]  = c;
            vsT[(I_IN + hu) * VST + b] = og * tanh_fast(c);
        }
        __syncthreads();
    }

    // ---- FC: out[b][o] = h_last . W_fc[o] + b_fc[o] ----
#pragma unroll
    for (int u = 0; u < 3; u++) {
        int idx = tid + u * NTHREADS;
        if (idx < BT * OUT) {
            int b = idx / OUT, o = idx % OUT;
            float a = bfcs[o];
            const float* wrow = &Wfcs[o * H];
#pragma unroll
            for (int j = 0; j < H; j++)
                a = fmaf(vsT[(I_IN + j) * VST + b], wrow[j], a);
            out[(size_t)(b0 + b) * OUT + o] = a;
        }
    }
}

extern "C" void kernel_launch(void* const* d_in, const int* in_sizes, int n_in,
                              void* d_out, int out_size)
{
    const float* x    = (const float*)d_in[0];
    const float* W_ih = (const float*)d_in[1];
    const float* W_hh = (const float*)d_in[2];
    const float* b_ih = (const float*)d_in[3];
    const float* b_hh = (const float*)d_in[4];
    const float* W_fc = (const float*)d_in[5];
    const float* b_fc = (const float*)d_in[6];
    float* out = (float*)d_out;

    const int smem_bytes = SMEM_FLOATS * (int)sizeof(float);
    cudaFuncSetAttribute(lstm_persistent_kernel,
                         cudaFuncAttributeMaxDynamicSharedMemorySize, smem_bytes);

    lstm_persistent_kernel<<<NCTAS, NTHREADS, smem_bytes>>>(
        x, W_ih, W_hh, b_ih, b_hh, W_fc, b_fc, out);
}

// round 17
// speedup vs baseline: 2.5986x; 2.5986x over previous
#include <cuda_runtime.h>
#include <cstdint>

// Problem constants
#define I_IN   21
#define H      50
#define G      200          // 4*H, gate order i,f,g,o
#define BATCH  4096
#define T      336
#define OUT    24
#define BT     32           // batch per CTA = M of the mma
#define VKS    76           // vs row stride (76 mod 32 = 12 -> conflict-free A-frag loads)
#define GST    33           // gsm row stride
#define NTHREADS 320        // 10 warps: 0-7 do mma, all do phase2
#define NCTAS  (BATCH / BT) // 128
#define NKT    9            // k-tiles of 8 covering k=0..71 (col 71 zero)
#define NNT    25           // n-tiles of 8 covering 200 gates exactly

// shared layout (floats)
#define OFF_VS   0                       // vs [BT][VKS] = 2432   state [x|h|pad], tf32-rounded
#define OFF_GSM  (OFF_VS + BT*VKS)       // gsm [G][GST] = 6600   activated gates
#define OFF_HS   (OFF_GSM + G*GST)       // hs  [BT][H]  = 1600   exact h (final step, for FC)
#define OFF_WFC  (OFF_HS + BT*H)         // 1200
#define OFF_BFC  (OFF_WFC + OUT*H)       // 24
#define SMEM_FLOATS (OFF_BFC + OUT)

__device__ __forceinline__ float tanh_fast(float x) {
    float y; asm("tanh.approx.f32 %0, %1;" : "=f"(y) : "f"(x)); return y;
}
// round fp32 -> tf32 (rna), result as fp32 bit pattern (low mantissa bits zeroed)
__device__ __forceinline__ float tf32f(float x) {
    uint32_t u; asm("cvt.rna.tf32.f32 %0, %1;" : "=r"(u) : "f"(x));
    return __uint_as_float(u);
}
__device__ __forceinline__ void mma_tf32(float (&d)[4], const uint32_t (&a)[4],
                                         const uint32_t (&b)[2]) {
    asm volatile(
        "mma.sync.aligned.m16n8k8.row.col.f32.tf32.tf32.f32 "
        "{%0,%1,%2,%3}, {%4,%5,%6,%7}, {%8,%9}, {%0,%1,%2,%3};"
        : "+f"(d[0]), "+f"(d[1]), "+f"(d[2]), "+f"(d[3])
        : "r"(a[0]), "r"(a[1]), "r"(a[2]), "r"(a[3]), "r"(b[0]), "r"(b[1]));
}

__device__ __forceinline__ float wc_load(const float* __restrict__ W_ih,
                                         const float* __restrict__ W_hh,
                                         int n, int k) {
    if (k < I_IN)        return W_ih[n * I_IN + k];
    if (k < I_IN + H)    return W_hh[n * H + (k - I_IN)];
    return 0.0f;
}

__global__ __launch_bounds__(NTHREADS, 1)
void lstm_mma_kernel(const float* __restrict__ x,
                     const float* __restrict__ W_ih,
                     const float* __restrict__ W_hh,
                     const float* __restrict__ b_ih,
                     const float* __restrict__ b_hh,
                     const float* __restrict__ W_fc,
                     const float* __restrict__ b_fc,
                     float* __restrict__ out)
{
    extern __shared__ float smem[];
    float* vs   = smem + OFF_VS;    // [BT][VKS]
    float* gsm  = smem + OFF_GSM;   // [G][GST]
    float* hs   = smem + OFF_HS;    // [BT][H]
    float* Wfcs = smem + OFF_WFC;
    float* bfcs = smem + OFF_BFC;

    const int tid  = threadIdx.x;
    const int lane = tid & 31;
    const int wid  = tid >> 5;
    const int b0   = blockIdx.x * BT;
    const int gid  = lane >> 2;     // mma group id (0..7)
    const int tidg = lane & 3;      // mma thread-in-group (0..3)

    // ---- one-time fills ----
    for (int idx = tid; idx < BT * VKS; idx += NTHREADS) vs[idx] = 0.0f;
    for (int idx = tid; idx < OUT * H; idx += NTHREADS)  Wfcs[idx] = W_fc[idx];
    if (tid < OUT) bfcs[tid] = b_fc[tid];

    // mma warps: load static B fragments (W^T), bias, activation params
    uint32_t Bf[4][NKT][2];
    float biasr[4][2];
    float sc[4], al[4], be[4];
    if (wid < 8) {
#pragma unroll
        for (int i = 0; i < 4; i++) {
            int tile = wid + 8 * i;
            if (tile < NNT) {
                int n = tile * 8 + gid;           // gate col (< 200)
#pragma unroll
                for (int kt = 0; kt < NKT; kt++) {
                    int k0 = kt * 8 + tidg;
                    Bf[i][kt][0] = __float_as_uint(tf32f(wc_load(W_ih, W_hh, n, k0)));
                    Bf[i][kt][1] = __float_as_uint(tf32f(wc_load(W_ih, W_hh, n, k0 + 4)));
                }
                int cb = tile * 8 + 2 * tidg;     // accumulator col pair base
                biasr[i][0] = b_ih[cb] + b_hh[cb];
                biasr[i][1] = b_ih[cb + 1] + b_hh[cb + 1];
                bool isg = (cb >= 2 * H) && (cb < 3 * H);   // g-gate -> tanh
                sc[i] = isg ? 1.0f : 0.5f;
                al[i] = isg ? 1.0f : 0.5f;
                be[i] = isg ? 0.0f : 0.5f;
            }
        }
    }
    __syncthreads();
    // x_0 into state (tf32-rounded)
    for (int idx = tid; idx < BT * I_IN; idx += NTHREADS) {
        int b = idx / I_IN, i = idx % I_IN;
        vs[b * VKS + i] = tf32f(x[(size_t)(b0 + b) * T * I_IN + i]);
    }
    __syncthreads();

    float creg[5];
#pragma unroll
    for (int j = 0; j < 5; j++) creg[j] = 0.0f;

    for (int t = 0; t < T; ++t) {
        // ---- prefetch x_{t+1} (round to tf32 in-flight) ----
        float xr[3];
        if (t + 1 < T) {
#pragma unroll
            for (int u = 0; u < 3; u++) {
                int idx = tid + u * NTHREADS;
                if (idx < BT * I_IN)
                    xr[u] = tf32f(x[(size_t)(b0 + idx / I_IN) * T * I_IN
                                    + (size_t)(t + 1) * I_IN + (idx % I_IN)]);
            }
        }

        // ---- phase 1: gates via mma (warps 0-7) ----
        if (wid < 8) {
            float acc[2][4][4];
#pragma unroll
            for (int mt = 0; mt < 2; mt++)
#pragma unroll
                for (int i = 0; i < 4; i++) {
                    acc[mt][i][0] = biasr[i][0];
                    acc[mt][i][1] = biasr[i][1];
                    acc[mt][i][2] = biasr[i][0];
                    acc[mt][i][3] = biasr[i][1];
                }
#pragma unroll
            for (int kt = 0; kt < NKT; kt++) {
                uint32_t Af[2][4];
#pragma unroll
                for (int mt = 0; mt < 2; mt++) {
                    int r = mt * 16 + gid;
                    int k = kt * 8 + tidg;
                    Af[mt][0] = __float_as_uint(vs[r * VKS + k]);
                    Af[mt][1] = __float_as_uint(vs[(r + 8) * VKS + k]);
                    Af[mt][2] = __float_as_uint(vs[r * VKS + k + 4]);
                    Af[mt][3] = __float_as_uint(vs[(r + 8) * VKS + k + 4]);
                }
#pragma unroll
                for (int i = 0; i < 4; i++) {
                    if (wid + 8 * i < NNT) {
                        mma_tf32(acc[0][i], Af[0], Bf[i][kt]);
                        mma_tf32(acc[1][i], Af[1], Bf[i][kt]);
                    }
                }
            }
            // activation + store to gsm[gate][batch]
#pragma unroll
            for (int i = 0; i < 4; i++) {
                if (wid + 8 * i < NNT) {
                    int cb = (wid + 8 * i) * 8 + 2 * tidg;
#pragma unroll
                    for (int mt = 0; mt < 2; mt++) {
                        int r = mt * 16 + gid;
                        gsm[cb * GST + r]           = fmaf(al[i], tanh_fast(sc[i] * acc[mt][i][0]), be[i]);
                        gsm[(cb + 1) * GST + r]     = fmaf(al[i], tanh_fast(sc[i] * acc[mt][i][1]), be[i]);
                        gsm[cb * GST + r + 8]       = fmaf(al[i], tanh_fast(sc[i] * acc[mt][i][2]), be[i]);
                        gsm[(cb + 1) * GST + r + 8] = fmaf(al[i], tanh_fast(sc[i] * acc[mt][i][3]), be[i]);
                    }
                }
            }
        }
        __syncthreads();

        // ---- phase 2: state update (+ commit x_{t+1}) ----
        if (t + 1 < T) {
#pragma unroll
            for (int u = 0; u < 3; u++) {
                int idx = tid + u * NTHREADS;
                if (idx < BT * I_IN)
                    vs[(idx / I_IN) * VKS + (idx % I_IN)] = xr[u];
            }
        }
#pragma unroll
        for (int j = 0; j < 5; j++) {
            int p  = tid * 5 + j;          // 0..1599
            int b  = p / H;
            int hu = p % H;
            float ig = gsm[hu * GST + b];
            float fg = gsm[(H + hu) * GST + b];
            float gg = gsm[(2 * H + hu) * GST + b];
            float og = gsm[(3 * H + hu) * GST + b];
            float c  = fmaf(fg, creg[j], ig * gg);
            creg[j]  = c;
            float hv = og * tanh_fast(c);
            vs[b * VKS + I_IN + hu] = tf32f(hv);
            if (t == T - 1) hs[b * H + hu] = hv;
        }
        __syncthreads();
    }

    // ---- FC: out[b][o] = h_last . W_fc[o] + b_fc[o]  (exact h) ----
#pragma unroll
    for (int u = 0; u < 3; u++) {
        int idx = tid + u * NTHREADS;
        if (idx < BT * OUT) {
            int b = idx / OUT, o = idx % OUT;
            float a = bfcs[o];
            const float* wrow = &Wfcs[o * H];
            const float* hrow = &hs[b * H];
#pragma unroll
            for (int j = 0; j < H; j++)
                a = fmaf(hrow[j], wrow[j], a);
            out[(size_t)(b0 + b) * OUT + o] = a;
        }
    }
}

extern "C" void kernel_launch(void* const* d_in, const int* in_sizes, int n_in,
                              void* d_out, int out_size)
{
    const float* x    = (const float*)d_in[0];
    const float* W_ih = (const float*)d_in[1];
    const float* W_hh = (const float*)d_in[2];
    const float* b_ih = (const float*)d_in[3];
    const float* b_hh = (const float*)d_in[4];
    const float* W_fc = (const float*)d_in[5];
    const float* b_fc = (const float*)d_in[6];
    float* out = (float*)d_out;

    const int smem_bytes = SMEM_FLOATS * (int)sizeof(float);
    cudaFuncSetAttribute(lstm_mma_kernel,
                         cudaFuncAttributeMaxDynamicSharedMemorySize, smem_bytes);
    lstm_mma_kernel<<<NCTAS, NTHREADS, smem_bytes>>>(
        x, W_ih, W_hh, b_ih, b_hh, W_fc, b_fc, out);
}